// round 1
// baseline (speedup 1.0000x reference)
#include <cuda_runtime.h>
#include <math.h>

#define N_NODES 50000
#define N_EDGES 800000
#define HDIM 96
#define SDIM 48
#define FDIM 24

// output layout: update[N*96] | fwd_w[E] | rev_w[E] | z[N*96] | r[N*96]
#define OFF_FW 4800000L
#define OFF_RW 5600000L
#define OFF_Z  6400000L
#define OFF_R  11200000L

// ---------------- scratch (__device__ globals; no allocation allowed) ----------------
__device__ float g_u[N_NODES * 144];          // [x | x_s]
__device__ float g_Wpack[768 * 144];          // node-projection weights [M=768, K=144]
__device__ float g_bpack[768];                // b1f baked into Sf, b1r into Br
__device__ float g_W1e[384 * 24];             // edge-feature projection weights
__device__ float g_table[N_NODES * 768];      // per node: Sf(192)|Br(192)|Df(192)|Ar(192)
__device__ float g_pe[N_EDGES * 384];         // per edge: pe_f(192)|pe_r(192)
__device__ float g_expf[N_EDGES];             // exp(score_fwd)
__device__ float g_ssum[N_NODES];             // softmax denominators
__device__ float g_fwdnum[N_NODES * HDIM];    // softmax-weighted numerator
__device__ float g_revagg[N_NODES * HDIM];    // sigmoid-weighted rev aggregation
__device__ float g_gatein[N_NODES * 288];
__device__ float g_candin[N_NODES * 288];
__device__ float g_h[N_NODES * 288];
__device__ float g_cand[N_NODES * HDIM];

// ---------------- small helpers ----------------
__device__ __forceinline__ void red4(float* p, float a, float b, float c, float d) {
    asm volatile("red.global.add.v4.f32 [%0], {%1,%2,%3,%4};"
                 :: "l"(p), "f"(a), "f"(b), "f"(c), "f"(d) : "memory");
}

// ---------------- weight packing ----------------
__global__ void pack_node_weights(const float* __restrict__ fwdW1, const float* __restrict__ revW1,
                                  const float* __restrict__ fwdb1, const float* __restrict__ revb1)
{
    int idx = blockIdx.x * blockDim.x + threadIdx.x;
    int total = 768 * 144;
    for (; idx < total; idx += gridDim.x * blockDim.x) {
        int j = idx / 144;     // output unit (0..767)
        int k = idx % 144;     // node-feature index: 0..95 -> x, 96..143 -> x_s
        float v;
        if (j < 192) {                       // Sf: fwd, "s" side
            v = (k < 96) ? fwdW1[j * 312 + k] : fwdW1[j * 312 + 192 + (k - 96)];
        } else if (j < 384) {                // Br: rev, "d" side (applied at src)
            int j2 = j - 192;
            v = (k < 96) ? revW1[j2 * 312 + 96 + k] : revW1[j2 * 312 + 240 + (k - 96)];
        } else if (j < 576) {                // Df: fwd, "d" side
            int j3 = j - 384;
            v = (k < 96) ? fwdW1[j3 * 312 + 96 + k] : fwdW1[j3 * 312 + 240 + (k - 96)];
        } else {                             // Ar: rev, "s" side (applied at dest)
            int j4 = j - 576;
            v = (k < 96) ? revW1[j4 * 312 + k] : revW1[j4 * 312 + 192 + (k - 96)];
        }
        g_Wpack[j * 144 + k] = v;
        if (k == 0) {
            g_bpack[j] = (j < 192) ? fwdb1[j] : ((j < 384) ? revb1[j - 192] : 0.0f);
        }
    }
}

__global__ void pack_edge_weights(const float* __restrict__ fwdW1, const float* __restrict__ revW1)
{
    int idx = blockIdx.x * blockDim.x + threadIdx.x;
    if (idx >= 384 * 24) return;
    int j = idx / 24, k = idx % 24;
    g_W1e[idx] = (j < 192) ? fwdW1[j * 312 + 288 + k] : revW1[(j - 192) * 312 + 288 + k];
}

__global__ void build_u(const float* __restrict__ x, const float* __restrict__ x_s)
{
    long idx = (long)blockIdx.x * blockDim.x + threadIdx.x;
    long total = (long)N_NODES * 144;
    for (; idx < total; idx += (long)gridDim.x * blockDim.x) {
        int n = (int)(idx / 144), c = (int)(idx % 144);
        g_u[idx] = (c < 96) ? x[(long)n * 96 + c] : x_s[(long)n * 48 + (c - 96)];
    }
}

__global__ void zero_accum()
{
    long idx = (long)blockIdx.x * blockDim.x + threadIdx.x;
    long total = (long)N_NODES * (1 + 2 * HDIM);
    for (; idx < total; idx += (long)gridDim.x * blockDim.x) {
        if (idx < N_NODES) g_ssum[idx] = 0.0f;
        else if (idx < (long)N_NODES * (1 + HDIM)) g_fwdnum[idx - N_NODES] = 0.0f;
        else g_revagg[idx - (long)N_NODES * (1 + HDIM)] = 0.0f;
    }
}

// ---------------- generic tiled fp32 GEMM: C = act(A[N,K] @ W[M,K]^T + bias) ----------------
#define GBM 64
#define GBN 32
#define GBK 8
// acts: 0=none 1=relu 2=sigmoid 3=tanh
__global__ __launch_bounds__(128)
void gemm_kernel(const float* __restrict__ A, const float* __restrict__ W,
                 const float* __restrict__ bias, float* __restrict__ C,
                 int Nrows, int K, int M, int act)
{
    __shared__ float sA[GBK][GBM + 4];
    __shared__ float sW[GBK][GBN + 4];
    int tid = threadIdx.x;
    int tx = tid & 7;          // 0..7  -> col group (4 cols each)
    int ty = tid >> 3;         // 0..15 -> row group (4 rows each)
    int row0 = blockIdx.y * GBM;
    int col0 = blockIdx.x * GBN;

    float acc[4][4];
#pragma unroll
    for (int i = 0; i < 4; i++)
#pragma unroll
        for (int j = 0; j < 4; j++) acc[i][j] = 0.0f;

    for (int k0 = 0; k0 < K; k0 += GBK) {
#pragma unroll
        for (int s0 = 0; s0 < GBM * GBK; s0 += 128) {
            int s = s0 + tid;
            int r = s >> 3, kk = s & 7;
            int gr = row0 + r;
            sA[kk][r] = (gr < Nrows) ? A[(long)gr * K + k0 + kk] : 0.0f;
        }
#pragma unroll
        for (int s0 = 0; s0 < GBN * GBK; s0 += 128) {
            int s = s0 + tid;
            if (s < GBN * GBK) {
                int c = s >> 3, kk = s & 7;
                sW[kk][c] = W[(long)(col0 + c) * K + k0 + kk];
            }
        }
        __syncthreads();
#pragma unroll
        for (int kk = 0; kk < GBK; kk++) {
            float a[4], w[4];
            *(float4*)a = *(const float4*)&sA[kk][ty * 4];
            *(float4*)w = *(const float4*)&sW[kk][tx * 4];
#pragma unroll
            for (int i = 0; i < 4; i++)
#pragma unroll
                for (int j = 0; j < 4; j++) acc[i][j] = fmaf(a[i], w[j], acc[i][j]);
        }
        __syncthreads();
    }

#pragma unroll
    for (int i = 0; i < 4; i++) {
        int gr = row0 + ty * 4 + i;
        if (gr >= Nrows) continue;
#pragma unroll
        for (int j = 0; j < 4; j++) {
            int gc = col0 + tx * 4 + j;
            float v = acc[i][j] + (bias ? bias[gc] : 0.0f);
            if (act == 1) v = fmaxf(v, 0.0f);
            else if (act == 2) v = 1.0f / (1.0f + expf(-v));
            else if (act == 3) v = tanhf(v);
            C[(long)gr * M + gc] = v;
        }
    }
}

// ---------------- edge kernel: one warp per edge ----------------
__global__ __launch_bounds__(256)
void edge_kernel(const int* __restrict__ ei, const float* __restrict__ x,
                 const float* __restrict__ fwdW2, const float* __restrict__ fwdb2,
                 const float* __restrict__ revW2, const float* __restrict__ revb2,
                 float* __restrict__ out)
{
    __shared__ float sW2f[192], sW2r[192];
    int tid = threadIdx.x;
    if (tid < 192) { sW2f[tid] = fwdW2[tid]; sW2r[tid] = revW2[tid]; }
    __syncthreads();

    long e = (long)blockIdx.x * 8 + (tid >> 5);
    if (e >= N_EDGES) return;
    int lane = tid & 31;

    int src = ei[e];
    int dst = ei[N_EDGES + e];
    const float* srow = g_table + (long)src * 768;
    const float* drow = g_table + (long)dst * 768;
    const float* pe = g_pe + e * 384;

    float dotf = 0.0f, dotr = 0.0f;
#pragma unroll
    for (int i = 0; i < 6; i++) {
        int j = lane + 32 * i;
        float hf = srow[j] + drow[384 + j] + pe[j];
        dotf = fmaf(fmaxf(hf, 0.0f), sW2f[j], dotf);
        float hr = srow[192 + j] + drow[576 + j] + pe[192 + j];
        dotr = fmaf(fmaxf(hr, 0.0f), sW2r[j], dotr);
    }
#pragma unroll
    for (int o = 16; o > 0; o >>= 1) {
        dotf += __shfl_down_sync(0xffffffffu, dotf, o);
        dotr += __shfl_down_sync(0xffffffffu, dotr, o);
    }

    float efv = 0.0f, wr = 0.0f;
    if (lane == 0) {
        float rawf = dotf + fwdb2[0];
        float score = (rawf >= 0.0f ? rawf : 0.01f * rawf) * (1.0f / sqrtf(96.0f));
        efv = expf(score);     // max-free softmax (scores are tiny; shift-invariant)
        float rawr = dotr + revb2[0];
        wr = 1.0f / (1.0f + expf(-rawr));
        g_expf[e] = efv;
        out[OFF_RW + e] = wr;
        atomicAdd(&g_ssum[dst], efv);
    }
    efv = __shfl_sync(0xffffffffu, efv, 0);
    wr  = __shfl_sync(0xffffffffu, wr, 0);

    if (lane < 24) {
        float4 xs = ((const float4*)x)[(long)src * 24 + lane];
        red4(&g_fwdnum[(long)dst * 96 + lane * 4], xs.x * efv, xs.y * efv, xs.z * efv, xs.w * efv);
        float4 xd = ((const float4*)x)[(long)dst * 24 + lane];
        red4(&g_revagg[(long)src * 96 + lane * 4], xd.x * wr, xd.y * wr, xd.z * wr, xd.w * wr);
    }
}

__global__ void fwdw_kernel(const int* __restrict__ ei, float* __restrict__ out)
{
    long e = (long)blockIdx.x * blockDim.x + threadIdx.x;
    if (e >= N_EDGES) return;
    int dst = ei[N_EDGES + e];
    out[OFF_FW + e] = g_expf[e] / (g_ssum[dst] + 1e-9f);
}

__global__ void build_gatein(const float* __restrict__ x)
{
    long idx = (long)blockIdx.x * blockDim.x + threadIdx.x;
    long total = (long)N_NODES * 288;
    for (; idx < total; idx += (long)gridDim.x * blockDim.x) {
        int n = (int)(idx / 288), c = (int)(idx % 288);
        float v;
        if (c < 96)       v = x[(long)n * 96 + c];
        else if (c < 192) v = g_fwdnum[(long)n * 96 + (c - 96)] / (g_ssum[n] + 1e-9f);
        else              v = g_revagg[(long)n * 96 + (c - 192)];
        g_gatein[idx] = v;
    }
}

__global__ void build_candin(const float* __restrict__ x, const float* __restrict__ out)
{
    long idx = (long)blockIdx.x * blockDim.x + threadIdx.x;
    long total = (long)N_NODES * 288;
    for (; idx < total; idx += (long)gridDim.x * blockDim.x) {
        int n = (int)(idx / 288), c = (int)(idx % 288);
        float v;
        if (c < 96) v = out[OFF_R + (long)n * 96 + c] * x[(long)n * 96 + c];
        else        v = g_gatein[idx];
        g_candin[idx] = v;
    }
}

__global__ void update_kernel(const float* __restrict__ x, float* __restrict__ out)
{
    long idx = (long)blockIdx.x * blockDim.x + threadIdx.x;
    long total = (long)N_NODES * 96;
    if (idx >= total) return;
    float z = out[OFF_Z + idx];
    out[idx] = (1.0f - z) * x[idx] + z * g_cand[idx];
}

// ---------------- launcher ----------------
extern "C" void kernel_launch(void* const* d_in, const int* in_sizes, int n_in,
                              void* d_out, int out_size)
{
    const float* x     = (const float*)d_in[0];
    const float* x_s   = (const float*)d_in[1];
    const float* efeat = (const float*)d_in[2];
    const int*   ei    = (const int*)d_in[3];
    const float* fwdW1 = (const float*)d_in[4];
    const float* fwdb1 = (const float*)d_in[5];
    const float* fwdW2 = (const float*)d_in[6];
    const float* fwdb2 = (const float*)d_in[7];
    const float* revW1 = (const float*)d_in[8];
    const float* revb1 = (const float*)d_in[9];
    const float* revW2 = (const float*)d_in[10];
    const float* revb2 = (const float*)d_in[11];
    const float* rstW1 = (const float*)d_in[12];
    const float* rstb1 = (const float*)d_in[13];
    const float* rstW2 = (const float*)d_in[14];
    const float* rstb2 = (const float*)d_in[15];
    const float* updW1 = (const float*)d_in[16];
    const float* updb1 = (const float*)d_in[17];
    const float* updW2 = (const float*)d_in[18];
    const float* updb2 = (const float*)d_in[19];
    const float* cndW1 = (const float*)d_in[20];
    const float* cndb1 = (const float*)d_in[21];
    const float* cndW2 = (const float*)d_in[22];
    const float* cndb2 = (const float*)d_in[23];
    float* out = (float*)d_out;

    float *p_u, *p_Wpack, *p_bpack, *p_W1e, *p_table, *p_pe, *p_gatein, *p_candin, *p_h, *p_cand;
    cudaGetSymbolAddress((void**)&p_u, g_u);
    cudaGetSymbolAddress((void**)&p_Wpack, g_Wpack);
    cudaGetSymbolAddress((void**)&p_bpack, g_bpack);
    cudaGetSymbolAddress((void**)&p_W1e, g_W1e);
    cudaGetSymbolAddress((void**)&p_table, g_table);
    cudaGetSymbolAddress((void**)&p_pe, g_pe);
    cudaGetSymbolAddress((void**)&p_gatein, g_gatein);
    cudaGetSymbolAddress((void**)&p_candin, g_candin);
    cudaGetSymbolAddress((void**)&p_h, g_h);
    cudaGetSymbolAddress((void**)&p_cand, g_cand);

    // 1. pack weights
    pack_node_weights<<<432, 256>>>(fwdW1, revW1, fwdb1, revb1);
    pack_edge_weights<<<36, 256>>>(fwdW1, revW1);
    build_u<<<7040, 256>>>(x, x_s);
    zero_accum<<<9432, 256>>>();

    // 2. node table: [N,144] @ [144,768]^T-style packed -> [N,768], bias baked
    {
        dim3 grid(768 / GBN, (N_NODES + GBM - 1) / GBM);
        gemm_kernel<<<grid, 128>>>(p_u, p_Wpack, p_bpack, p_table, N_NODES, 144, 768, 0);
    }
    // 3. edge-feature projection: [E,24] @ [24,384] -> [E,384]
    {
        dim3 grid(384 / GBN, (N_EDGES + GBM - 1) / GBM);
        gemm_kernel<<<grid, 128>>>(efeat, p_W1e, nullptr, p_pe, N_EDGES, 24, 384, 0);
    }
    // 4. edge pass: attention scores + aggregations
    edge_kernel<<<N_EDGES / 8, 256>>>(ei, x, fwdW2, fwdb2, revW2, revb2, out);
    // 5. normalized fwd weights
    fwdw_kernel<<<(N_EDGES + 255) / 256, 256>>>(ei, out);
    // 6. GRU
    build_gatein<<<14063, 256>>>(x);
    {
        dim3 g288(288 / GBN, (N_NODES + GBM - 1) / GBM);
        dim3 g96(96 / GBN, (N_NODES + GBM - 1) / GBM);
        gemm_kernel<<<g288, 128>>>(p_gatein, rstW1, rstb1, p_h, N_NODES, 288, 288, 1);
        gemm_kernel<<<g96, 128>>>(p_h, rstW2, rstb2, out + OFF_R, N_NODES, 288, 96, 2);
        gemm_kernel<<<g288, 128>>>(p_gatein, updW1, updb1, p_h, N_NODES, 288, 288, 1);
        gemm_kernel<<<g96, 128>>>(p_h, updW2, updb2, out + OFF_Z, N_NODES, 288, 96, 2);
        build_candin<<<14063, 256>>>(x, out);
        gemm_kernel<<<g288, 128>>>(p_candin, cndW1, cndb1, p_h, N_NODES, 288, 288, 1);
        gemm_kernel<<<g96, 128>>>(p_h, cndW2, cndb2, p_cand, N_NODES, 288, 96, 3);
    }
    update_kernel<<<(N_NODES * 96 + 255) / 256, 256>>>(x, out);
}